// round 5
// baseline (speedup 1.0000x reference)
#include <cuda_runtime.h>
#include <cuda_bf16.h>
#include <cstdint>
#include <cstddef>

#define Lc 512
#define Bc 64
#define Ec 512
#define Hc 512
#define Gc 2048   // 4*H

// ---------------- scratch (allocation-free: __device__ globals) ----------------
__device__ float    g_xproj[2ULL * Lc * Bc * Gc]; // [dir][t*B+b][4H], biases included
__device__ float    g_h[2][2][Bc * Hc];           // [dir][parity][b*H+u]
__device__ unsigned g_bar;

// ------------- packed f32x2 helpers (FFMA2: 2x fp32 FMA rate on sm_103a) -------
__device__ __forceinline__ unsigned long long ffma2(unsigned long long a,
                                                    unsigned long long b,
                                                    unsigned long long c) {
    unsigned long long d;
    asm("fma.rn.f32x2 %0, %1, %2, %3;" : "=l"(d) : "l"(a), "l"(b), "l"(c));
    return d;
}
__device__ __forceinline__ unsigned long long splat2(float x) {
    unsigned long long r;
    asm("mov.b64 %0, {%1, %1};" : "=l"(r) : "f"(x));
    return r;
}
__device__ __forceinline__ float2 unpack2(unsigned long long v) {
    float2 r;
    asm("mov.b64 {%0, %1}, %2;" : "=f"(r.x), "=f"(r.y) : "l"(v));
    return r;
}
__device__ __forceinline__ float sigmoidf_(float x) {
    return 1.0f / (1.0f + __expf(-x));
}

// ---------------- init: reset barrier + zero initial hidden state --------------
__global__ void k_init() {
    int idx = blockIdx.x * 256 + threadIdx.x;
    if (idx == 0) g_bar = 0u;
    if (idx < 2 * Bc * Hc) {
        int d = idx / (Bc * Hc);
        g_h[d][0][idx % (Bc * Hc)] = 0.0f;
    }
}

// ------- kernel 1: embedding gather + input projection GEMM (+ both biases) ----
// C[m][dir*2048+n] = emb[tok(m)] . W_ih_dir[n,:] + b_ih[n] + b_hh[n]
// M=32768 (m = t*64+b), N=4096 (dir-major), K=512. Tile 128x128x16, 256 thr, 8x8.
__global__ __launch_bounds__(256) void k_proj(
    const int*   __restrict__ tokens, const float* __restrict__ emb,
    const float* __restrict__ Wihf,   const float* __restrict__ Wihb,
    const float* __restrict__ bihf,   const float* __restrict__ bhhf,
    const float* __restrict__ bihb,   const float* __restrict__ bhhb)
{
    __shared__ __align__(16) float As[16][128];
    __shared__ __align__(16) float Bs[16][132];

    const int tid   = threadIdx.x;
    const int tx    = tid & 15;            // n sub-tile
    const int ty    = tid >> 4;            // m sub-tile
    const int nTile = blockIdx.x;          // 0..31
    const int dir   = nTile >> 4;
    const int nc0   = (nTile & 15) << 7;   // column base within direction
    const int mBase = blockIdx.y << 7;

    const float* __restrict__ W   = dir ? Wihb : Wihf;
    const float* __restrict__ bih = dir ? bihb : bihf;
    const float* __restrict__ bhh = dir ? bhhb : bhhf;

    // A loader: 2 float4/thread/stage, row gathered by token id
    const float4* aptr[2]; int amr[2], akq[2]; bool aval[2];
#pragma unroll
    for (int i = 0; i < 2; i++) {
        int aIdx = tid + i * 256;
        amr[i] = aIdx >> 2; akq[i] = aIdx & 3;
        int tok = tokens[mBase + amr[i]];
        aval[i] = (tok >= 0);
        aptr[i] = ((const float4*)(emb + (size_t)(aval[i] ? tok : 0) * Ec)) + akq[i];
    }
    // B loader: rows of W (row n has K=512 contiguous floats)
    const float4* bptr[2]; int bnr[2], bkq[2];
#pragma unroll
    for (int i = 0; i < 2; i++) {
        int bIdx = tid + i * 256;
        bnr[i] = bIdx >> 2; bkq[i] = bIdx & 3;
        bptr[i] = ((const float4*)(W + (size_t)(nc0 + bnr[i]) * Ec)) + bkq[i];
    }

    unsigned long long acc[8][4];
#pragma unroll
    for (int i = 0; i < 8; i++)
#pragma unroll
        for (int j = 0; j < 4; j++) acc[i][j] = 0ULL;

    for (int ks = 0; ks < 32; ks++) {
        float4 av[2], bv[2];
#pragma unroll
        for (int i = 0; i < 2; i++) {
            av[i] = aval[i] ? aptr[i][ks * 4] : make_float4(0.f, 0.f, 0.f, 0.f);
            bv[i] = bptr[i][ks * 4];
        }
        __syncthreads();
#pragma unroll
        for (int i = 0; i < 2; i++) {
            As[akq[i] * 4 + 0][amr[i]] = av[i].x;
            As[akq[i] * 4 + 1][amr[i]] = av[i].y;
            As[akq[i] * 4 + 2][amr[i]] = av[i].z;
            As[akq[i] * 4 + 3][amr[i]] = av[i].w;
            Bs[bkq[i] * 4 + 0][bnr[i]] = bv[i].x;
            Bs[bkq[i] * 4 + 1][bnr[i]] = bv[i].y;
            Bs[bkq[i] * 4 + 2][bnr[i]] = bv[i].z;
            Bs[bkq[i] * 4 + 3][bnr[i]] = bv[i].w;
        }
        __syncthreads();
#pragma unroll
        for (int kk = 0; kk < 16; kk++) {
            float4 a0 = *(const float4*)&As[kk][ty * 8];
            float4 a1 = *(const float4*)&As[kk][ty * 8 + 4];
            ulonglong2 b0 = *(const ulonglong2*)&Bs[kk][tx * 8];
            ulonglong2 b1 = *(const ulonglong2*)&Bs[kk][tx * 8 + 4];
            unsigned long long sp[8];
            sp[0] = splat2(a0.x); sp[1] = splat2(a0.y);
            sp[2] = splat2(a0.z); sp[3] = splat2(a0.w);
            sp[4] = splat2(a1.x); sp[5] = splat2(a1.y);
            sp[6] = splat2(a1.z); sp[7] = splat2(a1.w);
#pragma unroll
            for (int i = 0; i < 8; i++) {
                acc[i][0] = ffma2(sp[i], b0.x, acc[i][0]);
                acc[i][1] = ffma2(sp[i], b0.y, acc[i][1]);
                acc[i][2] = ffma2(sp[i], b1.x, acc[i][2]);
                acc[i][3] = ffma2(sp[i], b1.y, acc[i][3]);
            }
        }
    }

    // epilogue: add (b_ih + b_hh), store
    float bias[8];
#pragma unroll
    for (int j = 0; j < 8; j++) {
        int n = nc0 + tx * 8 + j;
        bias[j] = bih[n] + bhh[n];
    }
    float* xout = g_xproj + (size_t)dir * Lc * Bc * Gc;
#pragma unroll
    for (int i = 0; i < 8; i++) {
        int m = mBase + ty * 8 + i;
        float o8[8];
#pragma unroll
        for (int j = 0; j < 4; j++) {
            float2 v = unpack2(acc[i][j]);
            o8[2 * j]     = v.x + bias[2 * j];
            o8[2 * j + 1] = v.y + bias[2 * j + 1];
        }
        float4* dst = (float4*)(xout + (size_t)m * Gc + nc0 + tx * 8);
        dst[0] = make_float4(o8[0], o8[1], o8[2], o8[3]);
        dst[1] = make_float4(o8[4], o8[5], o8[6], o8[7]);
    }
}

// --------- kernel 2: persistent bidirectional LSTM recurrence ------------------
// 128 CTAs (1/SM, co-resident). CTA (dir, cid) owns hidden units u0..u0+7 of one
// direction: its 32 W_hh gate rows stay in smem for all 512 steps. Per step:
// broadcast h_prev (L2) -> smem, 64x32x512 GEMM via FFMA2, cell update, grid bar.
#define RNN_SMEM_BYTES ((32 * 512 + 64 * 512 + 32 * 65) * 4)
__global__ __launch_bounds__(256, 1) void k_rnn(
    const float* __restrict__ Whhf, const float* __restrict__ Whhb,
    const float* __restrict__ mask, float* __restrict__ out)
{
    extern __shared__ __align__(16) float smem[];
    float* Wsm = smem;                       // [kq 0..127][row 0..31] float4: 64 KB
    float* hsm = smem + 32 * 512;            // [b 0..63][k 0..511]: 128 KB
    float* gsm = smem + 32 * 512 + 64 * 512; // [row 0..31][65] padded

    const int tid  = threadIdx.x;
    const int lane = tid & 31;
    const int w    = tid >> 5;
    const int dir  = blockIdx.x >> 6;
    const int cid  = blockIdx.x & 63;
    const int u0   = cid << 3;

    const float* __restrict__ Whh = dir ? Whhb : Whhf;

    // Cache this CTA's 32 gate rows of W_hh (row r: gate g=r>>3, unit u0+(r&7))
    {
        float4* Wq = (float4*)Wsm;
        for (int idx = tid; idx < 32 * 128; idx += 256) {
            int r = idx >> 7, kq = idx & 127;
            int g = r >> 3, uu = r & 7;
            Wq[kq * 32 + r] =
                *(((const float4*)(Whh + (size_t)(g * Hc + u0 + uu) * Hc)) + kq);
        }
    }

    // Elementwise ownership: thread -> (batch eb, units euu, euu+1)
    const int eb  = tid >> 2;
    const int euu = (tid & 3) << 1;
    float creg0 = 0.0f, creg1 = 0.0f;
    int par = 0;

    const float* XP = g_xproj + (size_t)dir * Lc * Bc * Gc;

    const ulonglong2* hrow[8];
#pragma unroll
    for (int b8 = 0; b8 < 8; b8++)
        hrow[b8] = (const ulonglong2*)(hsm + (w * 8 + b8) * Hc);
    const ulonglong2* Wq2 = (const ulonglong2*)Wsm;

    for (int s = 0; s < Lc; s++) {
        const int t = dir ? (Lc - 1 - s) : s;

        // prefetch xproj (incl. biases) + mask for our items (hides DRAM latency)
        const float* xr = XP + ((size_t)t * Bc + eb) * Gc + (u0 + euu);
        float xp00 = xr[0],    xp01 = xr[1];
        float xp10 = xr[512],  xp11 = xr[513];
        float xp20 = xr[1024], xp21 = xr[1025];
        float xp30 = xr[1536], xp31 = xr[1537];
        float mk = mask[t * Bc + eb];

        // broadcast h_prev -> smem (L1-bypassed: cross-CTA coherence)
        {
            const float4* hb = (const float4*)(&g_h[dir][par][0]);
            float4* hq = (float4*)hsm;
            for (int i = tid; i < (Bc * Hc) / 4; i += 256)
                hq[i] = __ldcg(hb + i);
        }
        __syncthreads();

        // GEMM: gates[b][r] = h[b][:] . Whh_row(r). warp w -> batches w*8..+7,
        // lane -> row. FFMA2 over packed k-pairs.
        unsigned long long accl[8], acch[8];
#pragma unroll
        for (int b8 = 0; b8 < 8; b8++) { accl[b8] = 0ULL; acch[b8] = 0ULL; }
#pragma unroll 4
        for (int kq = 0; kq < 128; kq++) {
            ulonglong2 wv = Wq2[kq * 32 + lane];
#pragma unroll
            for (int b8 = 0; b8 < 8; b8++) {
                ulonglong2 hv = hrow[b8][kq];
                accl[b8] = ffma2(hv.x, wv.x, accl[b8]);
                acch[b8] = ffma2(hv.y, wv.y, acch[b8]);
            }
        }
#pragma unroll
        for (int b8 = 0; b8 < 8; b8++) {
            float2 x = unpack2(accl[b8]);
            float2 y = unpack2(acch[b8]);
            gsm[lane * 65 + (w * 8 + b8)] = (x.x + x.y) + (y.x + y.y);
        }
        __syncthreads();

        // LSTM cell for our two (eb, uu) items
        float gi0 = gsm[(euu)          * 65 + eb] + xp00;
        float gf0 = gsm[(8  + euu)     * 65 + eb] + xp10;
        float gg0 = gsm[(16 + euu)     * 65 + eb] + xp20;
        float go0 = gsm[(24 + euu)     * 65 + eb] + xp30;
        float gi1 = gsm[(euu + 1)      * 65 + eb] + xp01;
        float gf1 = gsm[(8  + euu + 1) * 65 + eb] + xp11;
        float gg1 = gsm[(16 + euu + 1) * 65 + eb] + xp21;
        float go1 = gsm[(24 + euu + 1) * 65 + eb] + xp31;

        float c0 = sigmoidf_(gf0) * creg0 + sigmoidf_(gi0) * tanhf(gg0);
        float h0 = sigmoidf_(go0) * tanhf(c0);
        float c1 = sigmoidf_(gf1) * creg1 + sigmoidf_(gi1) * tanhf(gg1);
        float h1 = sigmoidf_(go1) * tanhf(c1);
        h0 *= mk; c0 *= mk; h1 *= mk; c1 *= mk;
        creg0 = c0; creg1 = c1;

        float* hw = &g_h[dir][par ^ 1][eb * Hc + u0 + euu];
        hw[0] = h0; hw[1] = h1;
        float* ow = out + ((size_t)t * Bc + eb) * (2 * Hc) + dir * Hc + (u0 + euu);
        ow[0] = h0; ow[1] = h1;

        // grid-wide barrier: release (fence + block-sync + count), acquire (fence)
        __threadfence();
        __syncthreads();
        if (tid == 0) {
            unsigned target = (unsigned)(s + 1) * gridDim.x;
            atomicAdd(&g_bar, 1u);
            while (*((volatile unsigned*)&g_bar) < target) { }
        }
        __syncthreads();
        __threadfence();
        par ^= 1;
    }
}

// ---------------- launch --------------------------------------------------------
extern "C" void kernel_launch(void* const* d_in, const int* in_sizes, int n_in,
                              void* d_out, int out_size) {
    const int*   tokens = (const int*)  d_in[0];
    const float* mask   = (const float*)d_in[1];
    const float* emb    = (const float*)d_in[2];
    const float* Wihf   = (const float*)d_in[3];
    const float* Whhf   = (const float*)d_in[4];
    const float* bihf   = (const float*)d_in[5];
    const float* bhhf   = (const float*)d_in[6];
    const float* Wihb   = (const float*)d_in[7];
    const float* Whhb   = (const float*)d_in[8];
    const float* bihb   = (const float*)d_in[9];
    const float* bhhb   = (const float*)d_in[10];
    float* out = (float*)d_out;

    static bool attr_set = false;
    if (!attr_set) {
        cudaFuncSetAttribute(k_rnn, cudaFuncAttributeMaxDynamicSharedMemorySize,
                             RNN_SMEM_BYTES);
        attr_set = true;
    }

    k_init<<<(2 * Bc * Hc + 255) / 256, 256>>>();
    k_proj<<<dim3(32, (Lc * Bc) / 128), 256>>>(tokens, emb, Wihf, Wihb,
                                               bihf, bhhf, bihb, bhhb);
    k_rnn<<<128, 256, RNN_SMEM_BYTES>>>(Whhf, Whhb, mask, out);
}